// round 6
// baseline (speedup 1.0000x reference)
#include <cuda_runtime.h>
#include <cuda_fp16.h>
#include <math.h>
#include <stdint.h>

// ---------------- problem constants ----------------
#define RR 64
#define CC 256
#define EE 768
#define HH 12
#define DD 64
#define FF 3072
#define MM (RR*CC)          // 16384 tokens

// ---------------- scratch (device globals; no allocation allowed) ----------------
__device__ float g_x  [MM*EE];       // residual stream (fp32)
__device__ float g_h  [MM*EE];       // reused as __half
__device__ float g_q  [MM*EE];       // reused as __half
__device__ float g_k  [MM*EE];       // reused as __half
__device__ float g_v  [MM*EE];       // reused as __half
__device__ float g_ctx[MM*EE];       // reused as __half
__device__ float g_aw [HH*CC*RR*RR]; // fp32 attention weights
__device__ float g_ffn[MM*FF];       // reused as __half
__device__ float g_wt [9437184/2 + 64];  // transposed half weights

// ---------------- helpers ----------------
__device__ __forceinline__ uint32_t smem_to_u32(const void* p) {
    uint32_t a;
    asm("{ .reg .u64 t; cvta.to.shared.u64 t, %1; cvt.u32.u64 %0, t; }" : "=r"(a) : "l"(p));
    return a;
}
__device__ __forceinline__ void cp_async16(uint32_t saddr, const void* gptr) {
    asm volatile("cp.async.cg.shared.global [%0], [%1], 16;" :: "r"(saddr), "l"(gptr));
}
#define CP_COMMIT() asm volatile("cp.async.commit_group;" ::: "memory")
#define CP_WAIT1()  asm volatile("cp.async.wait_group 1;" ::: "memory")
#define CP_WAIT0()  asm volatile("cp.async.wait_group 0;" ::: "memory")

__device__ __forceinline__ void ldsm_x4(uint32_t* r, uint32_t addr) {
    asm volatile("ldmatrix.sync.aligned.m8n8.x4.shared.b16 {%0,%1,%2,%3}, [%4];"
        : "=r"(r[0]), "=r"(r[1]), "=r"(r[2]), "=r"(r[3]) : "r"(addr));
}

__device__ __forceinline__ void mma_f16(float* d, const uint32_t* a, uint32_t b0, uint32_t b1) {
    asm volatile("mma.sync.aligned.m16n8k16.row.col.f32.f16.f16.f32 "
        "{%0,%1,%2,%3}, {%4,%5,%6,%7}, {%8,%9}, {%0,%1,%2,%3};"
        : "+f"(d[0]), "+f"(d[1]), "+f"(d[2]), "+f"(d[3])
        : "r"(a[0]), "r"(a[1]), "r"(a[2]), "r"(a[3]), "r"(b0), "r"(b1));
}

// ---------------- gelu (tanh approx) ----------------
__device__ __forceinline__ float gelu_f(float x) {
    float x3 = x * x * x;
    return 0.5f * x * (1.0f + tanhf(0.7978845608028654f * (x + 0.044715f * x3)));
}

// ---------------- fp16 mma.sync GEMM v2 ----------------
// 128(m) x 256(n) block tile, BK=32 halves, 256 threads = 8 warps (2m x 4n), warp tile 64x64.
#define BM 128
#define BN 256
#define BKH 32
#define PITCH_H 40            // halves per smem row
#define A_STAGE_H (BM * PITCH_H)
#define B_STAGE_H (BN * PITCH_H)
#define STAGE_B ((A_STAGE_H + B_STAGE_H) * 2)
#define NSTAGE 3

__global__ void __launch_bounds__(256, 1) mma_gemm_f16(
    const __half* __restrict__ A, const __half* __restrict__ BT,
    const float* __restrict__ bias, const float* __restrict__ res,
    float* __restrict__ Cf, __half* __restrict__ Ch,
    int M, int N, int K, float scale, int act_gelu)
{
    extern __shared__ __half smh[];
    uint32_t sbase = smem_to_u32(smh);
    uint32_t AbufU[NSTAGE], BbufU[NSTAGE];
    #pragma unroll
    for (int s = 0; s < NSTAGE; s++) {
        AbufU[s] = sbase + (uint32_t)s * STAGE_B;
        BbufU[s] = AbufU[s] + A_STAGE_H * 2;
    }

    int tid = threadIdx.x;
    int wid = tid >> 5, lane = tid & 31;
    int g = lane >> 2, t = lane & 3;
    int wm = wid >> 2, wn = wid & 3;          // 2(m) x 4(n)
    int m0 = blockIdx.y * BM, n0 = blockIdx.x * BN;

    // ldmatrix byte offsets within a tile buffer
    int l16 = lane & 15;
    uint32_t a_koff = (uint32_t)(lane >> 4) * 16;
    uint32_t offA[4];
    #pragma unroll
    for (int mt = 0; mt < 4; mt++)
        offA[mt] = (uint32_t)((wm * 64 + mt * 16 + l16) * PITCH_H) * 2 + a_koff;
    int l8 = lane & 7;
    int b_half16 = (lane >> 3) & 1;
    int b_grp8 = lane >> 4;
    uint32_t offB[4];
    #pragma unroll
    for (int p = 0; p < 4; p++)
        offB[p] = (uint32_t)((wn * 64 + p * 16 + b_grp8 * 8 + l8) * PITCH_H) * 2 + (uint32_t)b_half16 * 16;

    float acc[4][8][4];
    #pragma unroll
    for (int i = 0; i < 4; i++)
        #pragma unroll
        for (int j = 0; j < 8; j++)
            #pragma unroll
            for (int c = 0; c < 4; c++) acc[i][j][c] = 0.f;

    const int NT = K / BKH;

    #define PREFETCH(kt, b) do {                                               \
        int k0p = (kt) * BKH;                                                  \
        _Pragma("unroll")                                                      \
        for (int i = 0; i < 2; i++) {                                          \
            int idx = i * 256 + tid;                                           \
            int row = idx >> 2, c8 = (idx & 3) * 8;                            \
            cp_async16(AbufU[b] + (uint32_t)(row * PITCH_H + c8) * 2,          \
                       A + (size_t)(m0 + row) * K + k0p + c8);                 \
        }                                                                      \
        _Pragma("unroll")                                                      \
        for (int i = 0; i < 4; i++) {                                          \
            int idx = i * 256 + tid;                                           \
            int row = idx >> 2, c8 = (idx & 3) * 8;                            \
            cp_async16(BbufU[b] + (uint32_t)(row * PITCH_H + c8) * 2,          \
                       BT + (size_t)(n0 + row) * K + k0p + c8);                \
        }                                                                      \
        CP_COMMIT();                                                           \
    } while (0)

    PREFETCH(0, 0);
    if (NT > 1) PREFETCH(1, 1);

    for (int kt = 0; kt < NT; kt++) {
        int b = kt % NSTAGE;
        if (kt + 1 < NT) CP_WAIT1(); else CP_WAIT0();
        __syncthreads();
        if (kt + 2 < NT) PREFETCH(kt + 2, (kt + 2) % NSTAGE);

        uint32_t Ab = AbufU[b], Bb = BbufU[b];
        #pragma unroll
        for (int ks = 0; ks < 2; ks++) {
            uint32_t koff = (uint32_t)ks * 32;     // 16 halves
            uint32_t af[4][4], bfr[4][4];
            #pragma unroll
            for (int mt = 0; mt < 4; mt++)
                ldsm_x4(af[mt], Ab + offA[mt] + koff);
            #pragma unroll
            for (int p = 0; p < 4; p++)
                ldsm_x4(bfr[p], Bb + offB[p] + koff);
            #pragma unroll
            for (int mt = 0; mt < 4; mt++)
                #pragma unroll
                for (int p = 0; p < 4; p++) {
                    mma_f16(acc[mt][2 * p    ], af[mt], bfr[p][0], bfr[p][1]);
                    mma_f16(acc[mt][2 * p + 1], af[mt], bfr[p][2], bfr[p][3]);
                }
        }
        __syncthreads();
    }
    #undef PREFETCH

    // epilogue
    #pragma unroll
    for (int mt = 0; mt < 4; mt++) {
        #pragma unroll
        for (int nt = 0; nt < 8; nt++) {
            int m = m0 + wm * 64 + mt * 16 + g;
            int n = n0 + wn * 64 + nt * 8 + 2 * t;
            float bx = bias[n], by = bias[n + 1];
            #pragma unroll
            for (int half = 0; half < 2; half++) {
                int mr = m + half * 8;
                float vx = (acc[mt][nt][half * 2 + 0] + bx) * scale;
                float vy = (acc[mt][nt][half * 2 + 1] + by) * scale;
                if (act_gelu) { vx = gelu_f(vx); vy = gelu_f(vy); }
                if (res) {
                    const float2 r2 = *(const float2*)(res + (size_t)mr * N + n);
                    vx += r2.x; vy += r2.y;
                }
                if (Cf) {
                    float2 o; o.x = vx; o.y = vy;
                    *(float2*)(Cf + (size_t)mr * N + n) = o;
                } else {
                    *(__half2*)(Ch + (size_t)mr * N + n) = __floats2half2_rn(vx, vy);
                }
            }
        }
    }
}

// ---------------- fused transpose of ALL 10 weights (fp32 [K][N] -> half [N][K]) ----------------
struct TPArgs {
    const float* src[10];
    __half* dst[10];
};
// weights 0-7: 768x768 (576 tiles each); 8: 768x3072 (2304); 9: 3072x768 (2304)
__global__ void transpose_all_kernel(TPArgs args) {
    __shared__ float tbuf[32][33];
    int bid = blockIdx.x;
    int w, tx, ty, K, N;
    if (bid < 4608)      { w = bid / 576; int tt = bid % 576;  K = 768;  N = 768;  tx = tt % 24; ty = tt / 24; }
    else if (bid < 6912) { w = 8;         int tt = bid - 4608; K = 768;  N = 3072; tx = tt % 96; ty = tt / 96; }
    else                 { w = 9;         int tt = bid - 6912; K = 3072; N = 768;  tx = tt % 24; ty = tt / 24; }
    const float* in = args.src[w];
    __half* out = args.dst[w];
    int x = tx * 32 + threadIdx.x;
    int y0 = ty * 32;
    #pragma unroll
    for (int i = threadIdx.y; i < 32; i += 8)
        tbuf[i][threadIdx.x] = in[(size_t)(y0 + i) * N + x];
    __syncthreads();
    int xo = ty * 32 + threadIdx.x;
    int yo0 = tx * 32;
    #pragma unroll
    for (int i = threadIdx.y; i < 32; i += 8)
        out[(size_t)(yo0 + i) * K + xo] = __float2half(tbuf[threadIdx.x][i]);
}

// ---------------- copy kernel (residual init) ----------------
__global__ void copy_kernel(const float4* __restrict__ in, float4* __restrict__ out, int n4) {
    int i = blockIdx.x * blockDim.x + threadIdx.x;
    if (i < n4) out[i] = in[i];
}

// ---------------- layernorm: fp32 in, half out ----------------
__global__ void ln_kernel(const float* __restrict__ x, const float* __restrict__ s,
                          const float* __restrict__ b, __half* __restrict__ out) {
    __shared__ float red[256];
    int t = threadIdx.x;
    const float* xr = x + (size_t)blockIdx.x * EE;
    float v0 = xr[t], v1 = xr[t + 256], v2 = xr[t + 512];
    red[t] = v0 + v1 + v2;
    __syncthreads();
    for (int o = 128; o; o >>= 1) { if (t < o) red[t] += red[t + o]; __syncthreads(); }
    float mean = red[0] * (1.0f / EE);
    __syncthreads();
    float d0 = v0 - mean, d1 = v1 - mean, d2 = v2 - mean;
    red[t] = d0 * d0 + d1 * d1 + d2 * d2;
    __syncthreads();
    for (int o = 128; o; o >>= 1) { if (t < o) red[t] += red[t + o]; __syncthreads(); }
    float rstd = rsqrtf(red[0] * (1.0f / EE) + 1e-6f);
    __half* orow = out + (size_t)blockIdx.x * EE;
    orow[t      ] = __float2half(d0 * rstd * s[t      ] + b[t      ]);
    orow[t + 256] = __float2half(d1 * rstd * s[t + 256] + b[t + 256]);
    orow[t + 512] = __float2half(d2 * rstd * s[t + 512] + b[t + 512]);
}

// unpack 8 halves (uint4) into smem row
__device__ __forceinline__ void unpack8(float* dst, uint4 raw) {
    __half2* hp = (__half2*)&raw;
    #pragma unroll
    for (int j = 0; j < 4; j++) {
        float2 f = __half22float2(hp[j]);
        dst[2 * j] = f.x; dst[2 * j + 1] = f.y;
    }
}

// ---------------- row attention scores ----------------
__global__ void __launch_bounds__(256) row_scores_kernel(
    const __half* __restrict__ q, const __half* __restrict__ k, float* __restrict__ aw)
{
    int h = blockIdx.z;
    int i0 = blockIdx.y * 32, j0 = blockIdx.x * 32;
    __shared__ float qs[32][65];
    __shared__ float ks[32][65];
    int tid = threadIdx.x;
    int ti = tid >> 4, tj = tid & 15;
    float a00 = 0.f, a01 = 0.f, a10 = 0.f, a11 = 0.f;

    int lrow = tid >> 3, lcol = (tid & 7) * 8;
    for (int r = 0; r < RR; r++) {
        uint4 rq = *(const uint4*)(q + ((size_t)((r * CC + i0 + lrow) * HH + h)) * DD + lcol);
        unpack8(&qs[lrow][lcol], rq);
        uint4 rk = *(const uint4*)(k + ((size_t)((r * CC + j0 + lrow) * HH + h)) * DD + lcol);
        unpack8(&ks[lrow][lcol], rk);
        __syncthreads();
        #pragma unroll 8
        for (int d = 0; d < DD; d++) {
            float q0 = qs[ti * 2][d], q1 = qs[ti * 2 + 1][d];
            float k0v = ks[tj * 2][d], k1v = ks[tj * 2 + 1][d];
            a00 = fmaf(q0, k0v, a00); a01 = fmaf(q0, k1v, a01);
            a10 = fmaf(q1, k0v, a10); a11 = fmaf(q1, k1v, a11);
        }
        __syncthreads();
    }
    size_t bbase = (size_t)h * CC * CC;
    aw[bbase + (size_t)(i0 + ti * 2    ) * CC + j0 + tj * 2    ] = a00;
    aw[bbase + (size_t)(i0 + ti * 2    ) * CC + j0 + tj * 2 + 1] = a01;
    aw[bbase + (size_t)(i0 + ti * 2 + 1) * CC + j0 + tj * 2    ] = a10;
    aw[bbase + (size_t)(i0 + ti * 2 + 1) * CC + j0 + tj * 2 + 1] = a11;
}

// ---------------- softmax over 256-wide rows ----------------
__global__ void softmax256_kernel(float* __restrict__ p) {
    __shared__ float red[256];
    int t = threadIdx.x;
    float* pr = p + (size_t)blockIdx.x * 256;
    float v = pr[t];
    red[t] = v;
    __syncthreads();
    for (int o = 128; o; o >>= 1) { if (t < o) red[t] = fmaxf(red[t], red[t + o]); __syncthreads(); }
    float mx = red[0];
    __syncthreads();
    float e = expf(v - mx);
    red[t] = e;
    __syncthreads();
    for (int o = 128; o; o >>= 1) { if (t < o) red[t] += red[t + o]; __syncthreads(); }
    pr[t] = e / red[0];
}

// ---------------- row attention context ----------------
__global__ void __launch_bounds__(256) row_ctx_kernel(
    const float* __restrict__ p, const __half* __restrict__ v, __half* __restrict__ ctx)
{
    int i0 = blockIdx.x * 32;
    int h = blockIdx.y;
    int r = blockIdx.z;
    int tid = threadIdx.x;
    int tx = tid & 63, ty = tid >> 6;
    __shared__ float ps[32][33];
    __shared__ float vs[32][65];
    float acc[8];
    #pragma unroll
    for (int u = 0; u < 8; u++) acc[u] = 0.f;

    int lrow = tid >> 3, lcol = (tid & 7) * 8;
    for (int jc = 0; jc < CC; jc += 32) {
        {
            int row = tid >> 3, col = (tid & 7) * 4;
            float4 vp = *(const float4*)(p + (size_t)h * CC * CC + (size_t)(i0 + row) * CC + jc + col);
            ps[row][col] = vp.x; ps[row][col + 1] = vp.y; ps[row][col + 2] = vp.z; ps[row][col + 3] = vp.w;
        }
        uint4 rv = *(const uint4*)(v + ((size_t)((r * CC + jc + lrow) * HH + h)) * DD + lcol);
        unpack8(&vs[lrow][lcol], rv);
        __syncthreads();
        #pragma unroll 8
        for (int j = 0; j < 32; j++) {
            float vv = vs[j][tx];
            #pragma unroll
            for (int u = 0; u < 8; u++)
                acc[u] = fmaf(ps[ty * 8 + u][j], vv, acc[u]);
        }
        __syncthreads();
    }
    #pragma unroll
    for (int u = 0; u < 8; u++)
        ctx[((size_t)((r * CC + i0 + ty * 8 + u) * HH + h)) * DD + tx] = __float2half(acc[u]);
}

// ---------------- column attention scores ----------------
__global__ void __launch_bounds__(256) col_scores_kernel(
    const __half* __restrict__ q, const __half* __restrict__ k, float* __restrict__ aw)
{
    int c = blockIdx.x, h = blockIdx.y;
    __shared__ float qs[64][65];
    __shared__ float ks[64][65];
    int tid = threadIdx.x;
    #pragma unroll
    for (int c4 = 0; c4 < 2; c4++) {
        int e = tid + 256 * c4;
        int row = e >> 3, col = (e & 7) * 8;
        uint4 rq = *(const uint4*)(q + ((size_t)((row * CC + c) * HH + h)) * DD + col);
        unpack8(&qs[row][col], rq);
        uint4 rk = *(const uint4*)(k + ((size_t)((row * CC + c) * HH + h)) * DD + col);
        unpack8(&ks[row][col], rk);
    }
    __syncthreads();
    int j = tid & 63, ib = (tid >> 6) * 16;
    float acc[16];
    #pragma unroll
    for (int u = 0; u < 16; u++) acc[u] = 0.f;
    #pragma unroll 4
    for (int d = 0; d < DD; d++) {
        float kv = ks[j][d];
        #pragma unroll
        for (int u = 0; u < 16; u++)
            acc[u] = fmaf(qs[ib + u][d], kv, acc[u]);
    }
    size_t bbase = ((size_t)h * CC + c) * RR * RR;
    #pragma unroll
    for (int u = 0; u < 16; u++)
        aw[bbase + (size_t)(ib + u) * RR + j] = acc[u];
}

// ---------------- softmax over 64-wide rows ----------------
__global__ void softmax64_kernel(float* __restrict__ p, int nrows) {
    int warp = (blockIdx.x * blockDim.x + threadIdx.x) >> 5;
    int lane = threadIdx.x & 31;
    if (warp >= nrows) return;
    float* pr = p + (size_t)warp * 64;
    float a = pr[lane], b = pr[lane + 32];
    float mx = fmaxf(a, b);
    #pragma unroll
    for (int o = 16; o; o >>= 1) mx = fmaxf(mx, __shfl_xor_sync(0xffffffffu, mx, o));
    a = expf(a - mx); b = expf(b - mx);
    float s = a + b;
    #pragma unroll
    for (int o = 16; o; o >>= 1) s += __shfl_xor_sync(0xffffffffu, s, o);
    float inv = 1.0f / s;
    pr[lane] = a * inv; pr[lane + 32] = b * inv;
}

// ---------------- column attention context ----------------
__global__ void __launch_bounds__(256) col_ctx_kernel(
    const float* __restrict__ p, const __half* __restrict__ v, __half* __restrict__ ctx)
{
    int c = blockIdx.x, h = blockIdx.y;
    __shared__ float ps[64][65];
    __shared__ float vs[64][65];
    int tid = threadIdx.x;
    size_t pbase = ((size_t)h * CC + c) * RR * RR;
    #pragma unroll
    for (int c4 = 0; c4 < 4; c4++) {
        int e4 = tid + 256 * c4;
        int row = e4 >> 4, col = (e4 & 15) * 4;
        float4 vp = *(const float4*)(p + pbase + (size_t)row * RR + col);
        ps[row][col] = vp.x; ps[row][col + 1] = vp.y; ps[row][col + 2] = vp.z; ps[row][col + 3] = vp.w;
    }
    #pragma unroll
    for (int c4 = 0; c4 < 2; c4++) {
        int e = tid + 256 * c4;
        int row = e >> 3, col = (e & 7) * 8;
        uint4 rv = *(const uint4*)(v + ((size_t)((row * CC + c) * HH + h)) * DD + col);
        unpack8(&vs[row][col], rv);
    }
    __syncthreads();
    int d = tid & 63, ib = (tid >> 6) * 16;
    float acc[16];
    #pragma unroll
    for (int u = 0; u < 16; u++) acc[u] = 0.f;
    #pragma unroll 4
    for (int j = 0; j < RR; j++) {
        float vv = vs[j][d];
        #pragma unroll
        for (int u = 0; u < 16; u++)
            acc[u] = fmaf(ps[ib + u][j], vv, acc[u]);
    }
    #pragma unroll
    for (int u = 0; u < 16; u++)
        ctx[((size_t)(((ib + u) * CC + c) * HH + h)) * DD + d] = __float2half(acc[u]);
}

// ---------------- host driver ----------------
#define GEMM_SMEM (NSTAGE * STAGE_B)   // 3 * 30720 = 92160 bytes

static void run_gemm(const __half* A, const __half* BT, const float* bias, const float* res,
                     float* Cf, __half* Ch, int M, int N, int K, float scale, int gelu) {
    dim3 grid(N / BN, M / BM);
    mma_gemm_f16<<<grid, 256, GEMM_SMEM>>>(A, BT, bias, res, Cf, Ch, M, N, K, scale, gelu);
}

extern "C" void kernel_launch(void* const* d_in, const int* in_sizes, int n_in,
                              void* d_out, int out_size) {
    const float* x_in = (const float*)d_in[0];
    const float* rq_w = (const float*)d_in[1];  const float* rq_b = (const float*)d_in[2];
    const float* rk_w = (const float*)d_in[3];  const float* rk_b = (const float*)d_in[4];
    const float* rv_w = (const float*)d_in[5];  const float* rv_b = (const float*)d_in[6];
    const float* ro_w = (const float*)d_in[7];  const float* ro_b = (const float*)d_in[8];
    const float* cq_w = (const float*)d_in[9];  const float* cq_b = (const float*)d_in[10];
    const float* ck_w = (const float*)d_in[11]; const float* ck_b = (const float*)d_in[12];
    const float* cv_w = (const float*)d_in[13]; const float* cv_b = (const float*)d_in[14];
    const float* co_w = (const float*)d_in[15]; const float* co_b = (const float*)d_in[16];
    const float* f1_w = (const float*)d_in[17]; const float* f1_b = (const float*)d_in[18];
    const float* f2_w = (const float*)d_in[19]; const float* f2_b = (const float*)d_in[20];
    const float* ln1_s = (const float*)d_in[21]; const float* ln1_b = (const float*)d_in[22];
    const float* ln2_s = (const float*)d_in[23]; const float* ln2_b = (const float*)d_in[24];
    const float* ln3_s = (const float*)d_in[25]; const float* ln3_b = (const float*)d_in[26];

    float *px, *paw;
    void *vh, *vq, *vk, *vv, *vctx, *vffn, *vwt;
    cudaGetSymbolAddress((void**)&px,   g_x);
    cudaGetSymbolAddress(&vh,   g_h);
    cudaGetSymbolAddress(&vq,   g_q);
    cudaGetSymbolAddress(&vk,   g_k);
    cudaGetSymbolAddress(&vv,   g_v);
    cudaGetSymbolAddress(&vctx, g_ctx);
    cudaGetSymbolAddress((void**)&paw,  g_aw);
    cudaGetSymbolAddress(&vffn, g_ffn);
    cudaGetSymbolAddress(&vwt,  g_wt);
    __half* ph   = (__half*)vh;
    __half* pq   = (__half*)vq;
    __half* pk   = (__half*)vk;
    __half* pv   = (__half*)vv;
    __half* pctx = (__half*)vctx;
    __half* pffn = (__half*)vffn;
    __half* pwt  = (__half*)vwt;

    cudaFuncSetAttribute(mma_gemm_f16, cudaFuncAttributeMaxDynamicSharedMemorySize, GEMM_SMEM);

    const size_t WEE = (size_t)EE * EE;
    __half* rqT = pwt + 0 * WEE;  __half* rkT = pwt + 1 * WEE;
    __half* rvT = pwt + 2 * WEE;  __half* roT = pwt + 3 * WEE;
    __half* cqT = pwt + 4 * WEE;  __half* ckT = pwt + 5 * WEE;
    __half* cvT = pwt + 6 * WEE;  __half* coT = pwt + 7 * WEE;
    __half* f1T = pwt + 8 * WEE;                     // [F][E]
    __half* f2T = f1T + (size_t)EE * FF;             // [E][F]

    // launch 1: all weight transposes (single kernel)
    {
        TPArgs a;
        a.src[0] = rq_w; a.dst[0] = rqT;
        a.src[1] = rk_w; a.dst[1] = rkT;
        a.src[2] = rv_w; a.dst[2] = rvT;
        a.src[3] = ro_w; a.dst[3] = roT;
        a.src[4] = cq_w; a.dst[4] = cqT;
        a.src[5] = ck_w; a.dst[5] = ckT;
        a.src[6] = cv_w; a.dst[6] = cvT;
        a.src[7] = co_w; a.dst[7] = coT;
        a.src[8] = f1_w; a.dst[8] = f1T;
        a.src[9] = f2_w; a.dst[9] = f2T;
        dim3 b(32, 8);
        transpose_all_kernel<<<9216, b>>>(a);
    }

    const float row_scale = 0.015625f;  // D^-0.5 * R^-0.5
    const float col_scale = 0.125f;     // D^-0.5

    // launch 2: residual init
    { int n4 = MM * EE / 4; copy_kernel<<<(n4 + 255) / 256, 256>>>((const float4*)x_in, (float4*)px, n4); }

    // ===== row attention =====
    ln_kernel<<<MM, 256>>>(px, ln1_s, ln1_b, ph);                              // 3
    run_gemm(ph, rqT, rq_b, nullptr, nullptr, pq, MM, EE, EE, row_scale, 0);   // 4
    run_gemm(ph, rkT, rk_b, nullptr, nullptr, pk, MM, EE, EE, 1.0f, 0);        // 5
    run_gemm(ph, rvT, rv_b, nullptr, nullptr, pv, MM, EE, EE, 1.0f, 0);        // 6 <- ncu captures this
    { dim3 g(CC / 32, CC / 32, HH); row_scores_kernel<<<g, 256>>>(pq, pk, paw); }
    softmax256_kernel<<<HH * CC, 256>>>(paw);
    { dim3 g(CC / 32, HH, RR); row_ctx_kernel<<<g, 256>>>(paw, pv, pctx); }
    run_gemm(pctx, roT, ro_b, px, px, nullptr, MM, EE, EE, 1.0f, 0);

    // ===== column attention =====
    ln_kernel<<<MM, 256>>>(px, ln2_s, ln2_b, ph);
    run_gemm(ph, cqT, cq_b, nullptr, nullptr, pq, MM, EE, EE, col_scale, 0);
    run_gemm(ph, ckT, ck_b, nullptr, nullptr, pk, MM, EE, EE, 1.0f, 0);
    run_gemm(ph, cvT, cv_b, nullptr, nullptr, pv, MM, EE, EE, 1.0f, 0);
    { dim3 g(CC, HH); col_scores_kernel<<<g, 256>>>(pq, pk, paw); }
    { int nrows = HH * CC * RR; softmax64_kernel<<<(nrows * 32 + 255) / 256, 256>>>(paw, nrows); }
    { dim3 g(CC, HH); col_ctx_kernel<<<g, 256>>>(paw, pv, pctx); }
    run_gemm(pctx, coT, co_b, px, px, nullptr, MM, EE, EE, 1.0f, 0);

    // ===== FFN =====
    ln_kernel<<<MM, 256>>>(px, ln3_s, ln3_b, ph);
    run_gemm(ph, f1T, f1_b, nullptr, nullptr, pffn, MM, FF, EE, 1.0f, 1);
    run_gemm(pffn, f2T, f2_b, px, (float*)d_out, nullptr, MM, EE, FF, 1.0f, 0);
}

// round 7
// speedup vs baseline: 1.1539x; 1.1539x over previous
#include <cuda_runtime.h>
#include <cuda_fp16.h>
#include <math.h>
#include <stdint.h>

// ---------------- problem constants ----------------
#define RR 64
#define CC 256
#define EE 768
#define HH 12
#define DD 64
#define FF 3072
#define MM (RR*CC)          // 16384 tokens
#define QLD 2304            // packed qkv row stride (halves)

// ---------------- scratch (device globals; no allocation allowed) ----------------
__device__ float g_x   [MM*EE];       // residual stream (fp32)
__device__ float g_h   [MM*EE];       // reused as __half
__device__ float g_ctx [MM*EE];       // reused as __half
__device__ float g_aw  [HH*CC*RR*RR]; // fp32 attention weights
__device__ float g_big [MM*FF];       // reused: qkv (half, MM*2304) then ffn h1 (half, MM*3072)
__device__ float g_wt  [9437184/2 + 64];  // transposed half weights
__device__ float g_bias[4608];        // packed row/col qkv biases

// ---------------- helpers ----------------
__device__ __forceinline__ uint32_t smem_to_u32(const void* p) {
    uint32_t a;
    asm("{ .reg .u64 t; cvta.to.shared.u64 t, %1; cvt.u32.u64 %0, t; }" : "=r"(a) : "l"(p));
    return a;
}
__device__ __forceinline__ void cp_async16(uint32_t saddr, const void* gptr) {
    asm volatile("cp.async.cg.shared.global [%0], [%1], 16;" :: "r"(saddr), "l"(gptr));
}
#define CP_COMMIT() asm volatile("cp.async.commit_group;" ::: "memory")
#define CP_WAIT1()  asm volatile("cp.async.wait_group 1;" ::: "memory")
#define CP_WAIT0()  asm volatile("cp.async.wait_group 0;" ::: "memory")

__device__ __forceinline__ void ldsm_x4(uint32_t* r, uint32_t addr) {
    asm volatile("ldmatrix.sync.aligned.m8n8.x4.shared.b16 {%0,%1,%2,%3}, [%4];"
        : "=r"(r[0]), "=r"(r[1]), "=r"(r[2]), "=r"(r[3]) : "r"(addr));
}

__device__ __forceinline__ void mma_f16(float* d, const uint32_t* a, uint32_t b0, uint32_t b1) {
    asm volatile("mma.sync.aligned.m16n8k16.row.col.f32.f16.f16.f32 "
        "{%0,%1,%2,%3}, {%4,%5,%6,%7}, {%8,%9}, {%0,%1,%2,%3};"
        : "+f"(d[0]), "+f"(d[1]), "+f"(d[2]), "+f"(d[3])
        : "r"(a[0]), "r"(a[1]), "r"(a[2]), "r"(a[3]), "r"(b0), "r"(b1));
}

// ---------------- gelu (tanh approx) ----------------
__device__ __forceinline__ float gelu_f(float x) {
    float x3 = x * x * x;
    return 0.5f * x * (1.0f + tanhf(0.7978845608028654f * (x + 0.044715f * x3)));
}

// ---------------- fp16 mma.sync GEMM: 128x128 tile, 8 warps (4m x 2n), warp 32x64 ----------------
#define BKH 32
#define PITCH_H 40
#define TILE_H (128 * PITCH_H)
#define NSTAGE 4

__global__ void __launch_bounds__(256, 2) mma_gemm_f16(
    const __half* __restrict__ A, const __half* __restrict__ BT,
    const float* __restrict__ bias, const float* __restrict__ res,
    float* __restrict__ Cf, __half* __restrict__ Ch,
    int M, int N, int K, int act_gelu)
{
    extern __shared__ __half smh[];
    uint32_t sbase = smem_to_u32(smh);
    uint32_t AbufU[NSTAGE], BbufU[NSTAGE];
    #pragma unroll
    for (int s = 0; s < NSTAGE; s++) {
        AbufU[s] = sbase + (uint32_t)(2 * s    ) * TILE_H * 2;
        BbufU[s] = sbase + (uint32_t)(2 * s + 1) * TILE_H * 2;
    }

    int tid = threadIdx.x;
    int wid = tid >> 5, lane = tid & 31;
    int g = lane >> 2, t = lane & 3;
    int wm = wid & 3, wn = wid >> 2;
    int m0 = blockIdx.y * 128, n0 = blockIdx.x * 128;

    int l16 = lane & 15;
    uint32_t a_koff = (uint32_t)(lane >> 4) * 16;
    uint32_t offA[2];
    #pragma unroll
    for (int mt = 0; mt < 2; mt++)
        offA[mt] = (uint32_t)((wm * 32 + mt * 16 + l16) * PITCH_H) * 2 + a_koff;
    int l8 = lane & 7;
    int b_half16 = (lane >> 3) & 1;
    int b_grp8 = lane >> 4;
    uint32_t offB[4];
    #pragma unroll
    for (int p = 0; p < 4; p++)
        offB[p] = (uint32_t)((wn * 64 + p * 16 + b_grp8 * 8 + l8) * PITCH_H) * 2 + (uint32_t)b_half16 * 16;

    float acc[2][8][4];
    #pragma unroll
    for (int i = 0; i < 2; i++)
        #pragma unroll
        for (int j = 0; j < 8; j++)
            #pragma unroll
            for (int c = 0; c < 4; c++) acc[i][j][c] = 0.f;

    const int NT = K / BKH;

    #define PREFETCH(kt, b) do {                                               \
        int k0p = (kt) * BKH;                                                  \
        _Pragma("unroll")                                                      \
        for (int i = 0; i < 2; i++) {                                          \
            int idx = i * 256 + tid;                                           \
            int row = idx >> 2, c8 = (idx & 3) * 8;                            \
            cp_async16(AbufU[b] + (uint32_t)(row * PITCH_H + c8) * 2,          \
                       A  + (size_t)(m0 + row) * K + k0p + c8);                \
            cp_async16(BbufU[b] + (uint32_t)(row * PITCH_H + c8) * 2,          \
                       BT + (size_t)(n0 + row) * K + k0p + c8);                \
        }                                                                      \
        CP_COMMIT();                                                           \
    } while (0)

    PREFETCH(0, 0);
    if (NT > 1) PREFETCH(1, 1);

    for (int kt = 0; kt < NT; kt++) {
        int b = kt % NSTAGE;
        if (kt + 1 < NT) CP_WAIT1(); else CP_WAIT0();
        __syncthreads();
        if (kt + 2 < NT) PREFETCH(kt + 2, (kt + 2) % NSTAGE);

        uint32_t Ab = AbufU[b], Bb = BbufU[b];
        #pragma unroll
        for (int ks = 0; ks < 2; ks++) {
            uint32_t koff = (uint32_t)ks * 32;
            uint32_t af[2][4], bfr[4][4];
            ldsm_x4(af[0], Ab + offA[0] + koff);
            ldsm_x4(af[1], Ab + offA[1] + koff);
            #pragma unroll
            for (int p = 0; p < 4; p++)
                ldsm_x4(bfr[p], Bb + offB[p] + koff);
            #pragma unroll
            for (int mt = 0; mt < 2; mt++)
                #pragma unroll
                for (int p = 0; p < 4; p++) {
                    mma_f16(acc[mt][2 * p    ], af[mt], bfr[p][0], bfr[p][1]);
                    mma_f16(acc[mt][2 * p + 1], af[mt], bfr[p][2], bfr[p][3]);
                }
        }
        __syncthreads();
    }
    #undef PREFETCH

    // epilogue (scales pre-folded into weights/bias)
    #pragma unroll
    for (int mt = 0; mt < 2; mt++) {
        #pragma unroll
        for (int nt = 0; nt < 8; nt++) {
            int m = m0 + wm * 32 + mt * 16 + g;
            int n = n0 + wn * 64 + nt * 8 + 2 * t;
            float bx = bias[n], by = bias[n + 1];
            #pragma unroll
            for (int half = 0; half < 2; half++) {
                int mr = m + half * 8;
                float vx = acc[mt][nt][half * 2 + 0] + bx;
                float vy = acc[mt][nt][half * 2 + 1] + by;
                if (act_gelu) { vx = gelu_f(vx); vy = gelu_f(vy); }
                if (res) {
                    const float2 r2 = *(const float2*)(res + (size_t)mr * N + n);
                    vx += r2.x; vy += r2.y;
                }
                if (Cf) {
                    float2 o; o.x = vx; o.y = vy;
                    *(float2*)(Cf + (size_t)mr * N + n) = o;
                } else {
                    *(__half2*)(Ch + (size_t)mr * N + n) = __floats2half2_rn(vx, vy);
                }
            }
        }
    }
}

// ---------------- fused transpose of ALL 10 weights (fp32 [K][N] -> half [N][K], scaled) ----------------
struct TPArgs {
    const float* src[10];
    __half* dst[10];
    float scale[10];
};
__global__ void transpose_all_kernel(TPArgs args) {
    __shared__ float tbuf[32][33];
    int bid = blockIdx.x;
    int w, tx, ty, K, N;
    if (bid < 4608)      { w = bid / 576; int tt = bid % 576;  K = 768;  N = 768;  tx = tt % 24; ty = tt / 24; }
    else if (bid < 6912) { w = 8;         int tt = bid - 4608; K = 768;  N = 3072; tx = tt % 96; ty = tt / 96; }
    else                 { w = 9;         int tt = bid - 6912; K = 3072; N = 768;  tx = tt % 24; ty = tt / 24; }
    const float* in = args.src[w];
    __half* out = args.dst[w];
    float sc = args.scale[w];
    int x = tx * 32 + threadIdx.x;
    int y0 = ty * 32;
    #pragma unroll
    for (int i = threadIdx.y; i < 32; i += 8)
        tbuf[i][threadIdx.x] = in[(size_t)(y0 + i) * N + x];
    __syncthreads();
    int xo = ty * 32 + threadIdx.x;
    int yo0 = tx * 32;
    #pragma unroll
    for (int i = threadIdx.y; i < 32; i += 8)
        out[(size_t)(yo0 + i) * K + xo] = __float2half(tbuf[threadIdx.x][i] * sc);
}

// ---------------- pack qkv bias: [qb*qs | kb | vb] ----------------
__global__ void pack_bias_kernel(const float* qb, const float* kb, const float* vb,
                                 float qs, float* out) {
    int i = blockIdx.x * blockDim.x + threadIdx.x;
    if (i < 768) out[i] = qb[i] * qs;
    else if (i < 1536) out[i] = kb[i - 768];
    else if (i < 2304) out[i] = vb[i - 1536];
}

// ---------------- copy kernel (residual init) ----------------
__global__ void copy_kernel(const float4* __restrict__ in, float4* __restrict__ out, int n4) {
    int i = blockIdx.x * blockDim.x + threadIdx.x;
    if (i < n4) out[i] = in[i];
}

// ---------------- layernorm: fp32 in, half out ----------------
__global__ void ln_kernel(const float* __restrict__ x, const float* __restrict__ s,
                          const float* __restrict__ b, __half* __restrict__ out) {
    __shared__ float red[256];
    int t = threadIdx.x;
    const float* xr = x + (size_t)blockIdx.x * EE;
    float v0 = xr[t], v1 = xr[t + 256], v2 = xr[t + 512];
    red[t] = v0 + v1 + v2;
    __syncthreads();
    for (int o = 128; o; o >>= 1) { if (t < o) red[t] += red[t + o]; __syncthreads(); }
    float mean = red[0] * (1.0f / EE);
    __syncthreads();
    float d0 = v0 - mean, d1 = v1 - mean, d2 = v2 - mean;
    red[t] = d0 * d0 + d1 * d1 + d2 * d2;
    __syncthreads();
    for (int o = 128; o; o >>= 1) { if (t < o) red[t] += red[t + o]; __syncthreads(); }
    float rstd = rsqrtf(red[0] * (1.0f / EE) + 1e-6f);
    __half* orow = out + (size_t)blockIdx.x * EE;
    orow[t      ] = __float2half(d0 * rstd * s[t      ] + b[t      ]);
    orow[t + 256] = __float2half(d1 * rstd * s[t + 256] + b[t + 256]);
    orow[t + 512] = __float2half(d2 * rstd * s[t + 512] + b[t + 512]);
}

// unpack 8 halves (uint4) into smem row
__device__ __forceinline__ void unpack8(float* dst, uint4 raw) {
    __half2* hp = (__half2*)&raw;
    #pragma unroll
    for (int j = 0; j < 4; j++) {
        float2 f = __half22float2(hp[j]);
        dst[2 * j] = f.x; dst[2 * j + 1] = f.y;
    }
}

// ---------------- row attention scores (qkv packed: stride QLD) ----------------
__global__ void __launch_bounds__(256) row_scores_kernel(
    const __half* __restrict__ q, const __half* __restrict__ k, float* __restrict__ aw)
{
    int h = blockIdx.z;
    int i0 = blockIdx.y * 32, j0 = blockIdx.x * 32;
    __shared__ float qs[32][65];
    __shared__ float ks[32][65];
    int tid = threadIdx.x;
    int ti = tid >> 4, tj = tid & 15;
    float a00 = 0.f, a01 = 0.f, a10 = 0.f, a11 = 0.f;

    int lrow = tid >> 3, lcol = (tid & 7) * 8;
    for (int r = 0; r < RR; r++) {
        uint4 rq = *(const uint4*)(q + (size_t)(r * CC + i0 + lrow) * QLD + h * DD + lcol);
        unpack8(&qs[lrow][lcol], rq);
        uint4 rk = *(const uint4*)(k + (size_t)(r * CC + j0 + lrow) * QLD + h * DD + lcol);
        unpack8(&ks[lrow][lcol], rk);
        __syncthreads();
        #pragma unroll 8
        for (int d = 0; d < DD; d++) {
            float q0 = qs[ti * 2][d], q1 = qs[ti * 2 + 1][d];
            float k0v = ks[tj * 2][d], k1v = ks[tj * 2 + 1][d];
            a00 = fmaf(q0, k0v, a00); a01 = fmaf(q0, k1v, a01);
            a10 = fmaf(q1, k0v, a10); a11 = fmaf(q1, k1v, a11);
        }
        __syncthreads();
    }
    size_t bbase = (size_t)h * CC * CC;
    aw[bbase + (size_t)(i0 + ti * 2    ) * CC + j0 + tj * 2    ] = a00;
    aw[bbase + (size_t)(i0 + ti * 2    ) * CC + j0 + tj * 2 + 1] = a01;
    aw[bbase + (size_t)(i0 + ti * 2 + 1) * CC + j0 + tj * 2    ] = a10;
    aw[bbase + (size_t)(i0 + ti * 2 + 1) * CC + j0 + tj * 2 + 1] = a11;
}

// ---------------- softmax over 256-wide rows ----------------
__global__ void softmax256_kernel(float* __restrict__ p) {
    __shared__ float red[256];
    int t = threadIdx.x;
    float* pr = p + (size_t)blockIdx.x * 256;
    float v = pr[t];
    red[t] = v;
    __syncthreads();
    for (int o = 128; o; o >>= 1) { if (t < o) red[t] = fmaxf(red[t], red[t + o]); __syncthreads(); }
    float mx = red[0];
    __syncthreads();
    float e = expf(v - mx);
    red[t] = e;
    __syncthreads();
    for (int o = 128; o; o >>= 1) { if (t < o) red[t] += red[t + o]; __syncthreads(); }
    pr[t] = e / red[0];
}

// ---------------- row attention context (v strided, ctx EE-layout half) ----------------
__global__ void __launch_bounds__(256) row_ctx_kernel(
    const float* __restrict__ p, const __half* __restrict__ v, __half* __restrict__ ctx)
{
    int i0 = blockIdx.x * 32;
    int h = blockIdx.y;
    int r = blockIdx.z;
    int tid = threadIdx.x;
    int tx = tid & 63, ty = tid >> 6;
    __shared__ float ps[32][33];
    __shared__ float vs[32][65];
    float acc[8];
    #pragma unroll
    for (int u = 0; u < 8; u++) acc[u] = 0.f;

    int lrow = tid >> 3, lcol = (tid & 7) * 8;
    for (int jc = 0; jc < CC; jc += 32) {
        {
            int row = tid >> 3, col = (tid & 7) * 4;
            float4 vp = *(const float4*)(p + (size_t)h * CC * CC + (size_t)(i0 + row) * CC + jc + col);
            ps[row][col] = vp.x; ps[row][col + 1] = vp.y; ps[row][col + 2] = vp.z; ps[row][col + 3] = vp.w;
        }
        uint4 rv = *(const uint4*)(v + (size_t)(r * CC + jc + lrow) * QLD + h * DD + lcol);
        unpack8(&vs[lrow][lcol], rv);
        __syncthreads();
        #pragma unroll 8
        for (int j = 0; j < 32; j++) {
            float vv = vs[j][tx];
            #pragma unroll
            for (int u = 0; u < 8; u++)
                acc[u] = fmaf(ps[ty * 8 + u][j], vv, acc[u]);
        }
        __syncthreads();
    }
    #pragma unroll
    for (int u = 0; u < 8; u++)
        ctx[((size_t)((r * CC + i0 + ty * 8 + u) * HH + h)) * DD + tx] = __float2half(acc[u]);
}

// ---------------- column attention scores ----------------
__global__ void __launch_bounds__(256) col_scores_kernel(
    const __half* __restrict__ q, const __half* __restrict__ k, float* __restrict__ aw)
{
    int c = blockIdx.x, h = blockIdx.y;
    __shared__ float qs[64][65];
    __shared__ float ks[64][65];
    int tid = threadIdx.x;
    #pragma unroll
    for (int c4 = 0; c4 < 2; c4++) {
        int e = tid + 256 * c4;
        int row = e >> 3, col = (e & 7) * 8;
        uint4 rq = *(const uint4*)(q + (size_t)(row * CC + c) * QLD + h * DD + col);
        unpack8(&qs[row][col], rq);
        uint4 rk = *(const uint4*)(k + (size_t)(row * CC + c) * QLD + h * DD + col);
        unpack8(&ks[row][col], rk);
    }
    __syncthreads();
    int j = tid & 63, ib = (tid >> 6) * 16;
    float acc[16];
    #pragma unroll
    for (int u = 0; u < 16; u++) acc[u] = 0.f;
    #pragma unroll 4
    for (int d = 0; d < DD; d++) {
        float kv = ks[j][d];
        #pragma unroll
        for (int u = 0; u < 16; u++)
            acc[u] = fmaf(qs[ib + u][d], kv, acc[u]);
    }
    size_t bbase = ((size_t)h * CC + c) * RR * RR;
    #pragma unroll
    for (int u = 0; u < 16; u++)
        aw[bbase + (size_t)(ib + u) * RR + j] = acc[u];
}

// ---------------- softmax over 64-wide rows ----------------
__global__ void softmax64_kernel(float* __restrict__ p, int nrows) {
    int warp = (blockIdx.x * blockDim.x + threadIdx.x) >> 5;
    int lane = threadIdx.x & 31;
    if (warp >= nrows) return;
    float* pr = p + (size_t)warp * 64;
    float a = pr[lane], b = pr[lane + 32];
    float mx = fmaxf(a, b);
    #pragma unroll
    for (int o = 16; o; o >>= 1) mx = fmaxf(mx, __shfl_xor_sync(0xffffffffu, mx, o));
    a = expf(a - mx); b = expf(b - mx);
    float s = a + b;
    #pragma unroll
    for (int o = 16; o; o >>= 1) s += __shfl_xor_sync(0xffffffffu, s, o);
    float inv = 1.0f / s;
    pr[lane] = a * inv; pr[lane + 32] = b * inv;
}

// ---------------- column attention context ----------------
__global__ void __launch_bounds__(256) col_ctx_kernel(
    const float* __restrict__ p, const __half* __restrict__ v, __half* __restrict__ ctx)
{
    int c = blockIdx.x, h = blockIdx.y;
    __shared__ float ps[64][65];
    __shared__ float vs[64][65];
    int tid = threadIdx.x;
    size_t pbase = ((size_t)h * CC + c) * RR * RR;
    #pragma unroll
    for (int c4 = 0; c4 < 4; c4++) {
        int e4 = tid + 256 * c4;
        int row = e4 >> 4, col = (e4 & 15) * 4;
        float4 vp = *(const float4*)(p + pbase + (size_t)row * RR + col);
        ps[row][col] = vp.x; ps[row][col + 1] = vp.y; ps[row][col + 2] = vp.z; ps[row][col + 3] = vp.w;
    }
    #pragma unroll
    for (int c4 = 0; c4 < 2; c4++) {
        int e = tid + 256 * c4;
        int row = e >> 3, col = (e & 7) * 8;
        uint4 rv = *(const uint4*)(v + (size_t)(row * CC + c) * QLD + h * DD + col);
        unpack8(&vs[row][col], rv);
    }
    __syncthreads();
    int d = tid & 63, ib = (tid >> 6) * 16;
    float acc[16];
    #pragma unroll
    for (int u = 0; u < 16; u++) acc[u] = 0.f;
    #pragma unroll 4
    for (int j = 0; j < RR; j++) {
        float vv = vs[j][d];
        #pragma unroll
        for (int u = 0; u < 16; u++)
            acc[u] = fmaf(ps[ib + u][j], vv, acc[u]);
    }
    #pragma unroll
    for (int u = 0; u < 16; u++)
        ctx[((size_t)(((ib + u) * CC + c) * HH + h)) * DD + d] = __float2half(acc[u]);
}

// ---------------- host driver ----------------
#define GEMM_SMEM (NSTAGE * 2 * TILE_H * 2)   // 4 * 20480 = 81920 bytes

static void run_gemm(const __half* A, const __half* BT, const float* bias, const float* res,
                     float* Cf, __half* Ch, int M, int N, int K, int gelu) {
    dim3 grid(N / 128, M / 128);
    mma_gemm_f16<<<grid, 256, GEMM_SMEM>>>(A, BT, bias, res, Cf, Ch, M, N, K, gelu);
}

extern "C" void kernel_launch(void* const* d_in, const int* in_sizes, int n_in,
                              void* d_out, int out_size) {
    const float* x_in = (const float*)d_in[0];
    const float* rq_w = (const float*)d_in[1];  const float* rq_b = (const float*)d_in[2];
    const float* rk_w = (const float*)d_in[3];  const float* rk_b = (const float*)d_in[4];
    const float* rv_w = (const float*)d_in[5];  const float* rv_b = (const float*)d_in[6];
    const float* ro_w = (const float*)d_in[7];  const float* ro_b = (const float*)d_in[8];
    const float* cq_w = (const float*)d_in[9];  const float* cq_b = (const float*)d_in[10];
    const float* ck_w = (const float*)d_in[11]; const float* ck_b = (const float*)d_in[12];
    const float* cv_w = (const float*)d_in[13]; const float* cv_b = (const float*)d_in[14];
    const float* co_w = (const float*)d_in[15]; const float* co_b = (const float*)d_in[16];
    const float* f1_w = (const float*)d_in[17]; const float* f1_b = (const float*)d_in[18];
    const float* f2_w = (const float*)d_in[19]; const float* f2_b = (const float*)d_in[20];
    const float* ln1_s = (const float*)d_in[21]; const float* ln1_b = (const float*)d_in[22];
    const float* ln2_s = (const float*)d_in[23]; const float* ln2_b = (const float*)d_in[24];
    const float* ln3_s = (const float*)d_in[25]; const float* ln3_b = (const float*)d_in[26];

    float *px, *paw, *pbias;
    void *vh, *vctx, *vbig, *vwt;
    cudaGetSymbolAddress((void**)&px,    g_x);
    cudaGetSymbolAddress(&vh,    g_h);
    cudaGetSymbolAddress(&vctx,  g_ctx);
    cudaGetSymbolAddress((void**)&paw,   g_aw);
    cudaGetSymbolAddress(&vbig,  g_big);
    cudaGetSymbolAddress(&vwt,   g_wt);
    cudaGetSymbolAddress((void**)&pbias, g_bias);
    __half* ph    = (__half*)vh;
    __half* pctx  = (__half*)vctx;
    __half* pqkv  = (__half*)vbig;       // [M][2304] during attention phases
    __half* pffn  = (__half*)vbig;       // [M][3072] during FFN (sequential reuse)
    __half* pwt   = (__half*)vwt;

    cudaFuncSetAttribute(mma_gemm_f16, cudaFuncAttributeMaxDynamicSharedMemorySize, GEMM_SMEM);

    const float row_scale = 0.015625f;  // D^-0.5 * R^-0.5
    const float col_scale = 0.125f;     // D^-0.5

    const size_t WEE = (size_t)EE * EE;
    __half* rqkvT = pwt;                      // rq,rk,rv contiguous: [2304][768]
    __half* roT   = pwt + 3 * WEE;
    __half* cqkvT = pwt + 4 * WEE;            // cq,ck,cv contiguous
    __half* coT   = pwt + 7 * WEE;
    __half* f1T   = pwt + 8 * WEE;            // [F][E]
    __half* f2T   = f1T + (size_t)EE * FF;    // [E][F]
    float* biasr = pbias;
    float* biasc = pbias + 2304;

    // launch 1: all weight transposes (scales folded into q-projection weights)
    {
        TPArgs a;
        a.src[0] = rq_w; a.dst[0] = pwt + 0 * WEE; a.scale[0] = row_scale;
        a.src[1] = rk_w; a.dst[1] = pwt + 1 * WEE; a.scale[1] = 1.f;
        a.src[2] = rv_w; a.dst[2] = pwt + 2 * WEE; a.scale[2] = 1.f;
        a.src[3] = ro_w; a.dst[3] = roT;           a.scale[3] = 1.f;
        a.src[4] = cq_w; a.dst[4] = pwt + 4 * WEE; a.scale[4] = col_scale;
        a.src[5] = ck_w; a.dst[5] = pwt + 5 * WEE; a.scale[5] = 1.f;
        a.src[6] = cv_w; a.dst[6] = pwt + 6 * WEE; a.scale[6] = 1.f;
        a.src[7] = co_w; a.dst[7] = coT;           a.scale[7] = 1.f;
        a.src[8] = f1_w; a.dst[8] = f1T;           a.scale[8] = 1.f;
        a.src[9] = f2_w; a.dst[9] = f2T;           a.scale[9] = 1.f;
        dim3 b(32, 8);
        transpose_all_kernel<<<9216, b>>>(a);
    }

    // launch 2-3: packed biases
    pack_bias_kernel<<<9, 256>>>(rq_b, rk_b, rv_b, row_scale, biasr);
    pack_bias_kernel<<<9, 256>>>(cq_b, ck_b, cv_b, col_scale, biasc);

    // launch 4: residual init
    { int n4 = MM * EE / 4; copy_kernel<<<(n4 + 255) / 256, 256>>>((const float4*)x_in, (float4*)px, n4); }

    // ===== row attention =====
    ln_kernel<<<MM, 256>>>(px, ln1_s, ln1_b, ph);                               // 5
    run_gemm(ph, rqkvT, biasr, nullptr, nullptr, pqkv, MM, QLD, EE, 0);         // 6 <- ncu
    { dim3 g(CC / 32, CC / 32, HH); row_scores_kernel<<<g, 256>>>(pqkv, pqkv + 768, paw); }
    softmax256_kernel<<<HH * CC, 256>>>(paw);
    { dim3 g(CC / 32, HH, RR); row_ctx_kernel<<<g, 256>>>(paw, pqkv + 1536, pctx); }
    run_gemm(pctx, roT, ro_b, px, px, nullptr, MM, EE, EE, 0);

    // ===== column attention =====
    ln_kernel<<<MM, 256>>>(px, ln2_s, ln2_b, ph);
    run_gemm(ph, cqkvT, biasc, nullptr, nullptr, pqkv, MM, QLD, EE, 0);
    { dim3 g(CC, HH); col_scores_kernel<<<g, 256>>>(pqkv, pqkv + 768, paw); }
    { int nrows = HH * CC * RR; softmax64_kernel<<<(nrows * 32 + 255) / 256, 256>>>(paw, nrows); }
    { dim3 g(CC, HH); col_ctx_kernel<<<g, 256>>>(paw, pqkv + 1536, pctx); }
    run_gemm(pctx, coT, co_b, px, px, nullptr, MM, EE, EE, 0);

    // ===== FFN =====
    ln_kernel<<<MM, 256>>>(px, ln3_s, ln3_b, ph);
    run_gemm(ph, f1T, f1_b, nullptr, nullptr, pffn, MM, FF, EE, 1);
    run_gemm(pffn, f2T, f2_b, px, (float*)d_out, nullptr, MM, EE, FF, 0);
}

// round 8
// speedup vs baseline: 1.7383x; 1.5065x over previous
#include <cuda_runtime.h>
#include <cuda_fp16.h>
#include <math.h>
#include <stdint.h>

// ---------------- problem constants ----------------
#define RR 64
#define CC 256
#define EE 768
#define HH 12
#define DD 64
#define FF 3072
#define MM (RR*CC)          // 16384 tokens
#define QLD 2304            // packed qkv row stride (halves)

// ---------------- scratch (device globals; no allocation allowed) ----------------
__device__ float g_x   [MM*EE];       // residual stream (fp32)
__device__ float g_h   [MM*EE];       // reused as __half
__device__ float g_ctx [MM*EE];       // reused as __half
__device__ float g_aw  [HH*CC*RR*RR]; // fp32 attention scores (p stored half in-place post-softmax)
__device__ float g_big [MM*FF];       // reused: qkv (half, MM*2304) then ffn h1 (half, MM*3072)
__device__ float g_wt  [9437184/2 + 64];  // transposed half weights
__device__ float g_bias[4608];        // packed row/col qkv biases

// ---------------- helpers ----------------
__device__ __forceinline__ uint32_t smem_to_u32(const void* p) {
    uint32_t a;
    asm("{ .reg .u64 t; cvta.to.shared.u64 t, %1; cvt.u32.u64 %0, t; }" : "=r"(a) : "l"(p));
    return a;
}
__device__ __forceinline__ void cp_async16(uint32_t saddr, const void* gptr) {
    asm volatile("cp.async.cg.shared.global [%0], [%1], 16;" :: "r"(saddr), "l"(gptr));
}
#define CP_COMMIT() asm volatile("cp.async.commit_group;" ::: "memory")
#define CP_WAIT1()  asm volatile("cp.async.wait_group 1;" ::: "memory")
#define CP_WAIT0()  asm volatile("cp.async.wait_group 0;" ::: "memory")

__device__ __forceinline__ void ldsm_x4(uint32_t* r, uint32_t addr) {
    asm volatile("ldmatrix.sync.aligned.m8n8.x4.shared.b16 {%0,%1,%2,%3}, [%4];"
        : "=r"(r[0]), "=r"(r[1]), "=r"(r[2]), "=r"(r[3]) : "r"(addr));
}
__device__ __forceinline__ void ldsm_x4_t(uint32_t* r, uint32_t addr) {
    asm volatile("ldmatrix.sync.aligned.m8n8.x4.trans.shared.b16 {%0,%1,%2,%3}, [%4];"
        : "=r"(r[0]), "=r"(r[1]), "=r"(r[2]), "=r"(r[3]) : "r"(addr));
}

__device__ __forceinline__ void mma_f16(float* d, const uint32_t* a, uint32_t b0, uint32_t b1) {
    asm volatile("mma.sync.aligned.m16n8k16.row.col.f32.f16.f16.f32 "
        "{%0,%1,%2,%3}, {%4,%5,%6,%7}, {%8,%9}, {%0,%1,%2,%3};"
        : "+f"(d[0]), "+f"(d[1]), "+f"(d[2]), "+f"(d[3])
        : "r"(a[0]), "r"(a[1]), "r"(a[2]), "r"(a[3]), "r"(b0), "r"(b1));
}

// ---------------- gelu (tanh approx) ----------------
__device__ __forceinline__ float gelu_f(float x) {
    float x3 = x * x * x;
    return 0.5f * x * (1.0f + tanhf(0.7978845608028654f * (x + 0.044715f * x3)));
}

// ---------------- fp16 mma.sync GEMM: 128x128 tile, 8 warps (4m x 2n), warp 32x64 ----------------
#define BKH 32
#define PITCH_H 40
#define TILE_H (128 * PITCH_H)
#define NSTAGE 4

__global__ void __launch_bounds__(256, 2) mma_gemm_f16(
    const __half* __restrict__ A, const __half* __restrict__ BT,
    const float* __restrict__ bias, const float* __restrict__ res,
    float* __restrict__ Cf, __half* __restrict__ Ch,
    int M, int N, int K, int act_gelu)
{
    extern __shared__ __half smh[];
    uint32_t sbase = smem_to_u32(smh);
    uint32_t AbufU[NSTAGE], BbufU[NSTAGE];
    #pragma unroll
    for (int s = 0; s < NSTAGE; s++) {
        AbufU[s] = sbase + (uint32_t)(2 * s    ) * TILE_H * 2;
        BbufU[s] = sbase + (uint32_t)(2 * s + 1) * TILE_H * 2;
    }

    int tid = threadIdx.x;
    int wid = tid >> 5, lane = tid & 31;
    int g = lane >> 2, t = lane & 3;
    int wm = wid & 3, wn = wid >> 2;
    int m0 = blockIdx.y * 128, n0 = blockIdx.x * 128;

    int l16 = lane & 15;
    uint32_t a_koff = (uint32_t)(lane >> 4) * 16;
    uint32_t offA[2];
    #pragma unroll
    for (int mt = 0; mt < 2; mt++)
        offA[mt] = (uint32_t)((wm * 32 + mt * 16 + l16) * PITCH_H) * 2 + a_koff;
    int l8 = lane & 7;
    int b_half16 = (lane >> 3) & 1;
    int b_grp8 = lane >> 4;
    uint32_t offB[4];
    #pragma unroll
    for (int p = 0; p < 4; p++)
        offB[p] = (uint32_t)((wn * 64 + p * 16 + b_grp8 * 8 + l8) * PITCH_H) * 2 + (uint32_t)b_half16 * 16;

    float acc[2][8][4];
    #pragma unroll
    for (int i = 0; i < 2; i++)
        #pragma unroll
        for (int j = 0; j < 8; j++)
            #pragma unroll
            for (int c = 0; c < 4; c++) acc[i][j][c] = 0.f;

    const int NT = K / BKH;

    #define PREFETCH(kt, b) do {                                               \
        int k0p = (kt) * BKH;                                                  \
        _Pragma("unroll")                                                      \
        for (int i = 0; i < 2; i++) {                                          \
            int idx = i * 256 + tid;                                           \
            int row = idx >> 2, c8 = (idx & 3) * 8;                            \
            cp_async16(AbufU[b] + (uint32_t)(row * PITCH_H + c8) * 2,          \
                       A  + (size_t)(m0 + row) * K + k0p + c8);                \
            cp_async16(BbufU[b] + (uint32_t)(row * PITCH_H + c8) * 2,          \
                       BT + (size_t)(n0 + row) * K + k0p + c8);                \
        }                                                                      \
        CP_COMMIT();                                                           \
    } while (0)

    PREFETCH(0, 0);
    if (NT > 1) PREFETCH(1, 1);

    for (int kt = 0; kt < NT; kt++) {
        int b = kt % NSTAGE;
        if (kt + 1 < NT) CP_WAIT1(); else CP_WAIT0();
        __syncthreads();
        if (kt + 2 < NT) PREFETCH(kt + 2, (kt + 2) % NSTAGE);

        uint32_t Ab = AbufU[b], Bb = BbufU[b];
        #pragma unroll
        for (int ks = 0; ks < 2; ks++) {
            uint32_t koff = (uint32_t)ks * 32;
            uint32_t af[2][4], bfr[4][4];
            ldsm_x4(af[0], Ab + offA[0] + koff);
            ldsm_x4(af[1], Ab + offA[1] + koff);
            #pragma unroll
            for (int p = 0; p < 4; p++)
                ldsm_x4(bfr[p], Bb + offB[p] + koff);
            #pragma unroll
            for (int mt = 0; mt < 2; mt++)
                #pragma unroll
                for (int p = 0; p < 4; p++) {
                    mma_f16(acc[mt][2 * p    ], af[mt], bfr[p][0], bfr[p][1]);
                    mma_f16(acc[mt][2 * p + 1], af[mt], bfr[p][2], bfr[p][3]);
                }
        }
        __syncthreads();
    }
    #undef PREFETCH

    #pragma unroll
    for (int mt = 0; mt < 2; mt++) {
        #pragma unroll
        for (int nt = 0; nt < 8; nt++) {
            int m = m0 + wm * 32 + mt * 16 + g;
            int n = n0 + wn * 64 + nt * 8 + 2 * t;
            float bx = bias[n], by = bias[n + 1];
            #pragma unroll
            for (int half = 0; half < 2; half++) {
                int mr = m + half * 8;
                float vx = acc[mt][nt][half * 2 + 0] + bx;
                float vy = acc[mt][nt][half * 2 + 1] + by;
                if (act_gelu) { vx = gelu_f(vx); vy = gelu_f(vy); }
                if (res) {
                    const float2 r2 = *(const float2*)(res + (size_t)mr * N + n);
                    vx += r2.x; vy += r2.y;
                }
                if (Cf) {
                    float2 o; o.x = vx; o.y = vy;
                    *(float2*)(Cf + (size_t)mr * N + n) = o;
                } else {
                    *(__half2*)(Ch + (size_t)mr * N + n) = __floats2half2_rn(vx, vy);
                }
            }
        }
    }
}

// ---------------- fused transpose of ALL 10 weights ----------------
struct TPArgs {
    const float* src[10];
    __half* dst[10];
    float scale[10];
};
__global__ void transpose_all_kernel(TPArgs args) {
    __shared__ float tbuf[32][33];
    int bid = blockIdx.x;
    int w, tx, ty, K, N;
    if (bid < 4608)      { w = bid / 576; int tt = bid % 576;  K = 768;  N = 768;  tx = tt % 24; ty = tt / 24; }
    else if (bid < 6912) { w = 8;         int tt = bid - 4608; K = 768;  N = 3072; tx = tt % 96; ty = tt / 96; }
    else                 { w = 9;         int tt = bid - 6912; K = 3072; N = 768;  tx = tt % 24; ty = tt / 24; }
    const float* in = args.src[w];
    __half* out = args.dst[w];
    float sc = args.scale[w];
    int x = tx * 32 + threadIdx.x;
    int y0 = ty * 32;
    #pragma unroll
    for (int i = threadIdx.y; i < 32; i += 8)
        tbuf[i][threadIdx.x] = in[(size_t)(y0 + i) * N + x];
    __syncthreads();
    int xo = ty * 32 + threadIdx.x;
    int yo0 = tx * 32;
    #pragma unroll
    for (int i = threadIdx.y; i < 32; i += 8)
        out[(size_t)(yo0 + i) * K + xo] = __float2half(tbuf[threadIdx.x][i] * sc);
}

// ---------------- pack qkv bias ----------------
__global__ void pack_bias_kernel(const float* qb, const float* kb, const float* vb,
                                 float qs, float* out) {
    int i = blockIdx.x * blockDim.x + threadIdx.x;
    if (i < 768) out[i] = qb[i] * qs;
    else if (i < 1536) out[i] = kb[i - 768];
    else if (i < 2304) out[i] = vb[i - 1536];
}

// ---------------- copy kernel ----------------
__global__ void copy_kernel(const float4* __restrict__ in, float4* __restrict__ out, int n4) {
    int i = blockIdx.x * blockDim.x + threadIdx.x;
    if (i < n4) out[i] = in[i];
}

// ---------------- layernorm: fp32 in, half out ----------------
__global__ void ln_kernel(const float* __restrict__ x, const float* __restrict__ s,
                          const float* __restrict__ b, __half* __restrict__ out) {
    __shared__ float red[256];
    int t = threadIdx.x;
    const float* xr = x + (size_t)blockIdx.x * EE;
    float v0 = xr[t], v1 = xr[t + 256], v2 = xr[t + 512];
    red[t] = v0 + v1 + v2;
    __syncthreads();
    for (int o = 128; o; o >>= 1) { if (t < o) red[t] += red[t + o]; __syncthreads(); }
    float mean = red[0] * (1.0f / EE);
    __syncthreads();
    float d0 = v0 - mean, d1 = v1 - mean, d2 = v2 - mean;
    red[t] = d0 * d0 + d1 * d1 + d2 * d2;
    __syncthreads();
    for (int o = 128; o; o >>= 1) { if (t < o) red[t] += red[t + o]; __syncthreads(); }
    float rstd = rsqrtf(red[0] * (1.0f / EE) + 1e-6f);
    __half* orow = out + (size_t)blockIdx.x * EE;
    orow[t      ] = __float2half(d0 * rstd * s[t      ] + b[t      ]);
    orow[t + 256] = __float2half(d1 * rstd * s[t + 256] + b[t + 256]);
    orow[t + 512] = __float2half(d2 * rstd * s[t + 512] + b[t + 512]);
}

// ================= tensor-core attention =================
#define AP 72   // smem pitch (halves) for 64-wide attention tiles

// ---- row scores: aw[h,i,j] = sum_{r,d} q.k ; CTA = 64i x 64j per head, r-loop ----
__global__ void __launch_bounds__(256) row_scores_mma(
    const __half* __restrict__ qkv, float* __restrict__ aw)
{
    __shared__ __half qs[2][64 * AP];
    __shared__ __half ks[2][64 * AP];
    int h = blockIdx.z;
    int i0 = blockIdx.y * 64, j0 = blockIdx.x * 64;
    int tid = threadIdx.x;
    int wid = tid >> 5, lane = tid & 31;
    int g = lane >> 2, t = lane & 3;
    int wm = wid & 3, wn = wid >> 2;     // 4(i) x 2(j); warp tile i16 x j32
    uint32_t qb[2] = { smem_to_u32(qs[0]), smem_to_u32(qs[1]) };
    uint32_t kb[2] = { smem_to_u32(ks[0]), smem_to_u32(ks[1]) };

    int l16 = lane & 15;
    uint32_t offA = (uint32_t)((wm * 16 + l16) * AP) * 2 + (uint32_t)(lane >> 4) * 16;
    int l8 = lane & 7;
    int bh = (lane >> 3) & 1, bg = lane >> 4;
    uint32_t offB[2];
    #pragma unroll
    for (int p = 0; p < 2; p++)
        offB[p] = (uint32_t)((wn * 32 + p * 16 + bg * 8 + l8) * AP) * 2 + (uint32_t)bh * 16;

    float acc[4][4];
    #pragma unroll
    for (int i = 0; i < 4; i++)
        #pragma unroll
        for (int c = 0; c < 4; c++) acc[i][c] = 0.f;

    int lrow = tid >> 2, lc8 = (tid & 3) * 16;

    #define LOADRS(r, b) do {                                                     \
        const __half* qr = qkv + (size_t)((r) * CC + i0 + lrow) * QLD + h * DD;    \
        const __half* kr = qkv + 768 + (size_t)((r) * CC + j0 + lrow) * QLD + h * DD; \
        cp_async16(qb[b] + (uint32_t)(lrow * AP + lc8) * 2,     qr + lc8);         \
        cp_async16(qb[b] + (uint32_t)(lrow * AP + lc8 + 8) * 2, qr + lc8 + 8);     \
        cp_async16(kb[b] + (uint32_t)(lrow * AP + lc8) * 2,     kr + lc8);         \
        cp_async16(kb[b] + (uint32_t)(lrow * AP + lc8 + 8) * 2, kr + lc8 + 8);     \
        CP_COMMIT();                                                               \
    } while (0)

    LOADRS(0, 0);
    for (int r = 0; r < RR; r++) {
        if (r + 1 < RR) { LOADRS(r + 1, (r + 1) & 1); CP_WAIT1(); } else CP_WAIT0();
        __syncthreads();
        int b = r & 1;
        #pragma unroll
        for (int ks_ = 0; ks_ < 4; ks_++) {
            uint32_t koff = (uint32_t)ks_ * 32;
            uint32_t af[4], bf0[4], bf1[4];
            ldsm_x4(af, qb[b] + offA + koff);
            ldsm_x4(bf0, kb[b] + offB[0] + koff);
            ldsm_x4(bf1, kb[b] + offB[1] + koff);
            mma_f16(acc[0], af, bf0[0], bf0[1]);
            mma_f16(acc[1], af, bf0[2], bf0[3]);
            mma_f16(acc[2], af, bf1[0], bf1[1]);
            mma_f16(acc[3], af, bf1[2], bf1[3]);
        }
        __syncthreads();
    }
    #undef LOADRS

    size_t base = (size_t)h * CC * CC;
    #pragma unroll
    for (int nt = 0; nt < 4; nt++) {
        int n = j0 + wn * 32 + (nt >> 1) * 16 + (nt & 1) * 8 + 2 * t;
        #pragma unroll
        for (int hf = 0; hf < 2; hf++) {
            int m = i0 + wm * 16 + g + hf * 8;
            float2 o; o.x = acc[nt][hf * 2]; o.y = acc[nt][hf * 2 + 1];
            *(float2*)(aw + base + (size_t)m * CC + n) = o;
        }
    }
}

// ---- col scores: aw2[h,c,i,j] = sum_d q.k ; one CTA per (h,c), 64x64x64 ----
__global__ void __launch_bounds__(256) col_scores_mma(
    const __half* __restrict__ qkv, float* __restrict__ aw)
{
    __shared__ __half qs[64 * AP];
    __shared__ __half ks[64 * AP];
    int c = blockIdx.x, h = blockIdx.y;
    int tid = threadIdx.x;
    int wid = tid >> 5, lane = tid & 31;
    int g = lane >> 2, t = lane & 3;
    int wm = wid & 3, wn = wid >> 2;
    uint32_t qb = smem_to_u32(qs), kb = smem_to_u32(ks);

    int lrow = tid >> 2, lc8 = (tid & 3) * 16;
    {
        const __half* qr = qkv + (size_t)(lrow * CC + c) * QLD + h * DD;
        const __half* kr = qkv + 768 + (size_t)(lrow * CC + c) * QLD + h * DD;
        cp_async16(qb + (uint32_t)(lrow * AP + lc8) * 2,     qr + lc8);
        cp_async16(qb + (uint32_t)(lrow * AP + lc8 + 8) * 2, qr + lc8 + 8);
        cp_async16(kb + (uint32_t)(lrow * AP + lc8) * 2,     kr + lc8);
        cp_async16(kb + (uint32_t)(lrow * AP + lc8 + 8) * 2, kr + lc8 + 8);
        CP_COMMIT(); CP_WAIT0();
    }
    __syncthreads();

    int l16 = lane & 15;
    uint32_t offA = (uint32_t)((wm * 16 + l16) * AP) * 2 + (uint32_t)(lane >> 4) * 16;
    int l8 = lane & 7;
    int bh = (lane >> 3) & 1, bg = lane >> 4;
    uint32_t offB[2];
    #pragma unroll
    for (int p = 0; p < 2; p++)
        offB[p] = (uint32_t)((wn * 32 + p * 16 + bg * 8 + l8) * AP) * 2 + (uint32_t)bh * 16;

    float acc[4][4];
    #pragma unroll
    for (int i = 0; i < 4; i++)
        #pragma unroll
        for (int cc2 = 0; cc2 < 4; cc2++) acc[i][cc2] = 0.f;

    #pragma unroll
    for (int ks_ = 0; ks_ < 4; ks_++) {
        uint32_t koff = (uint32_t)ks_ * 32;
        uint32_t af[4], bf0[4], bf1[4];
        ldsm_x4(af, qb + offA + koff);
        ldsm_x4(bf0, kb + offB[0] + koff);
        ldsm_x4(bf1, kb + offB[1] + koff);
        mma_f16(acc[0], af, bf0[0], bf0[1]);
        mma_f16(acc[1], af, bf0[2], bf0[3]);
        mma_f16(acc[2], af, bf1[0], bf1[1]);
        mma_f16(acc[3], af, bf1[2], bf1[3]);
    }

    size_t base = ((size_t)h * CC + c) * RR * RR;
    #pragma unroll
    for (int nt = 0; nt < 4; nt++) {
        int n = wn * 32 + (nt >> 1) * 16 + (nt & 1) * 8 + 2 * t;
        #pragma unroll
        for (int hf = 0; hf < 2; hf++) {
            int m = wm * 16 + g + hf * 8;
            float2 o; o.x = acc[nt][hf * 2]; o.y = acc[nt][hf * 2 + 1];
            *(float2*)(aw + base + (size_t)m * RR + n) = o;
        }
    }
}

// ---- softmax 256-wide, writes HALF in-place ----
__global__ void softmax256_kernel(float* __restrict__ p) {
    __shared__ float red[256];
    int t = threadIdx.x;
    float* pr = p + (size_t)blockIdx.x * 256;
    float v = pr[t];
    red[t] = v;
    __syncthreads();
    for (int o = 128; o; o >>= 1) { if (t < o) red[t] = fmaxf(red[t], red[t + o]); __syncthreads(); }
    float mx = red[0];
    __syncthreads();
    float e = expf(v - mx);
    red[t] = e;
    __syncthreads();
    for (int o = 128; o; o >>= 1) { if (t < o) red[t] += red[t + o]; __syncthreads(); }
    float inv = 1.0f / red[0];
    __syncthreads();                       // all reads of pr done
    ((__half*)pr)[t] = __float2half(e * inv);
}

// ---- softmax 64-wide (one warp per row), writes HALF in-place ----
__global__ void softmax64_kernel(float* __restrict__ p, int nrows) {
    int warp = (blockIdx.x * blockDim.x + threadIdx.x) >> 5;
    int lane = threadIdx.x & 31;
    if (warp >= nrows) return;
    float* pr = p + (size_t)warp * 64;
    float a = pr[lane], b = pr[lane + 32];
    float mx = fmaxf(a, b);
    #pragma unroll
    for (int o = 16; o; o >>= 1) mx = fmaxf(mx, __shfl_xor_sync(0xffffffffu, mx, o));
    a = expf(a - mx); b = expf(b - mx);
    float s = a + b;
    #pragma unroll
    for (int o = 16; o; o >>= 1) s += __shfl_xor_sync(0xffffffffu, s, o);
    float inv = 1.0f / s;
    __half* ph = (__half*)pr;
    ph[lane] = __float2half(a * inv); ph[lane + 32] = __float2half(b * inv);
}

// ---- row ctx: ctx[r,i,h,:] = sum_j p[h,i,j] v[r,j,h,:] ; CTA = 128i x 64d per (h,r) ----
__global__ void __launch_bounds__(256) row_ctx_mma(
    const float* __restrict__ paw, const __half* __restrict__ qkv, __half* __restrict__ ctx)
{
    __shared__ __half ps[128 * AP];
    __shared__ __half vs[64 * AP];
    int i0 = blockIdx.x * 128;
    int r = blockIdx.y, h = blockIdx.z;
    int tid = threadIdx.x;
    int wid = tid >> 5, lane = tid & 31;
    int g = lane >> 2, t = lane & 3;
    int wm = wid & 3, wn = wid >> 2;    // 4(i) x 2(d); warp tile i32 x d32
    uint32_t pb = smem_to_u32(ps), vb = smem_to_u32(vs);
    const __half* ph_g = (const __half*)paw;   // half p, row stride 512 halves

    int l16 = lane & 15;
    uint32_t offA[2];
    #pragma unroll
    for (int mt = 0; mt < 2; mt++)
        offA[mt] = (uint32_t)((wm * 32 + mt * 16 + l16) * AP) * 2 + (uint32_t)(lane >> 4) * 16;
    int lr = lane & 7, sel = lane >> 3;
    uint32_t offBT[2];
    #pragma unroll
    for (int ng = 0; ng < 2; ng++)
        offBT[ng] = (uint32_t)(((sel & 1) * 8 + lr) * AP) * 2
                  + (uint32_t)(wn * 32 + ng * 16 + (sel >> 1) * 8) * 2;

    float acc[2][4][4];
    #pragma unroll
    for (int i = 0; i < 2; i++)
        #pragma unroll
        for (int j = 0; j < 4; j++)
            #pragma unroll
            for (int c = 0; c < 4; c++) acc[i][j][c] = 0.f;

    int prow = tid >> 1, pc0 = (tid & 1) * 32;
    int vrow = tid >> 2, vc8 = (tid & 3) * 16;

    for (int jc = 0; jc < CC; jc += 64) {
        const __half* pg = ph_g + (size_t)h * 131072 + (size_t)(i0 + prow) * 512 + jc;
        #pragma unroll
        for (int q = 0; q < 4; q++)
            cp_async16(pb + (uint32_t)(prow * AP + pc0 + q * 8) * 2, pg + pc0 + q * 8);
        const __half* vg = qkv + 1536 + (size_t)(r * CC + jc + vrow) * QLD + h * DD;
        cp_async16(vb + (uint32_t)(vrow * AP + vc8) * 2,     vg + vc8);
        cp_async16(vb + (uint32_t)(vrow * AP + vc8 + 8) * 2, vg + vc8 + 8);
        CP_COMMIT(); CP_WAIT0();
        __syncthreads();

        #pragma unroll
        for (int ks_ = 0; ks_ < 4; ks_++) {
            uint32_t koffA = (uint32_t)ks_ * 32;            // 16 halves along j
            uint32_t koffB = (uint32_t)(ks_ * 16 * AP) * 2; // 16 rows of V
            uint32_t af[2][4], bt0[4], bt1[4];
            ldsm_x4(af[0], pb + offA[0] + koffA);
            ldsm_x4(af[1], pb + offA[1] + koffA);
            ldsm_x4_t(bt0, vb + offBT[0] + koffB);
            ldsm_x4_t(bt1, vb + offBT[1] + koffB);
            #pragma unroll
            for (int mt = 0; mt < 2; mt++) {
                mma_f16(acc[mt][0], af[mt], bt0[0], bt0[1]);
                mma_f16(acc[mt][1], af[mt], bt0[2], bt0[3]);
                mma_f16(acc[mt][2], af[mt], bt1[0], bt1[1]);
                mma_f16(acc[mt][3], af[mt], bt1[2], bt1[3]);
            }
        }
        __syncthreads();
    }

    #pragma unroll
    for (int mt = 0; mt < 2; mt++) {
        #pragma unroll
        for (int nt = 0; nt < 4; nt++) {
            int d = h * DD + wn * 32 + (nt >> 1) * 16 + (nt & 1) * 8 + 2 * t;
            #pragma unroll
            for (int hf = 0; hf < 2; hf++) {
                int m = i0 + wm * 32 + mt * 16 + g + hf * 8;
                *(__half2*)(ctx + (size_t)(r * CC + m) * EE + d) =
                    __floats2half2_rn(acc[mt][nt][hf * 2], acc[mt][nt][hf * 2 + 1]);
            }
        }
    }
}

// ---- col ctx: ctx[i,c,h,:] = sum_j p2[h,c,i,j] v[j,c,h,:] ; one CTA per (h,c) ----
__global__ void __launch_bounds__(256) col_ctx_mma(
    const float* __restrict__ paw, const __half* __restrict__ qkv, __half* __restrict__ ctx)
{
    __shared__ __half ps[64 * AP];
    __shared__ __half vs[64 * AP];
    int c = blockIdx.x, h = blockIdx.y;
    int tid = threadIdx.x;
    int wid = tid >> 5, lane = tid & 31;
    int g = lane >> 2, t = lane & 3;
    int wm = wid & 3, wn = wid >> 2;   // warp tile i16 x d32
    uint32_t pb = smem_to_u32(ps), vb = smem_to_u32(vs);
    const __half* ph_g = (const __half*)paw;   // half p, row stride 128 halves

    int lrow = tid >> 2, lc8 = (tid & 3) * 16;
    {
        const __half* pg = ph_g + (((size_t)h * CC + c) * 4096 + (size_t)lrow * 64) * 2;
        cp_async16(pb + (uint32_t)(lrow * AP + lc8) * 2,     pg + lc8);
        cp_async16(pb + (uint32_t)(lrow * AP + lc8 + 8) * 2, pg + lc8 + 8);
        const __half* vg = qkv + 1536 + (size_t)(lrow * CC + c) * QLD + h * DD;
        cp_async16(vb + (uint32_t)(lrow * AP + lc8) * 2,     vg + lc8);
        cp_async16(vb + (uint32_t)(lrow * AP + lc8 + 8) * 2, vg + lc8 + 8);
        CP_COMMIT(); CP_WAIT0();
    }
    __syncthreads();

    int l16 = lane & 15;
    uint32_t offA = (uint32_t)((wm * 16 + l16) * AP) * 2 + (uint32_t)(lane >> 4) * 16;
    int lr = lane & 7, sel = lane >> 3;
    uint32_t offBT[2];
    #pragma unroll
    for (int ng = 0; ng < 2; ng++)
        offBT[ng] = (uint32_t)(((sel & 1) * 8 + lr) * AP) * 2
                  + (uint32_t)(wn * 32 + ng * 16 + (sel >> 1) * 8) * 2;

    float acc[4][4];
    #pragma unroll
    for (int i = 0; i < 4; i++)
        #pragma unroll
        for (int cc2 = 0; cc2 < 4; cc2++) acc[i][cc2] = 0.f;

    #pragma unroll
    for (int ks_ = 0; ks_ < 4; ks_++) {
        uint32_t koffA = (uint32_t)ks_ * 32;
        uint32_t koffB = (uint32_t)(ks_ * 16 * AP) * 2;
        uint32_t af[4], bt0[4], bt1[4];
        ldsm_x4(af, pb + offA + koffA);
        ldsm_x4_t(bt0, vb + offBT[0] + koffB);
        ldsm_x4_t(bt1, vb + offBT[1] + koffB);
        mma_f16(acc[0], af, bt0[0], bt0[1]);
        mma_f16(acc[1], af, bt0[2], bt0[3]);
        mma_f16(acc[2], af, bt1[0], bt1[1]);
        mma_f16(acc[3], af, bt1[2], bt1[3]);
    }

    #pragma unroll
    for (int nt = 0; nt < 4; nt++) {
        int d = h * DD + wn * 32 + (nt >> 1) * 16 + (nt & 1) * 8 + 2 * t;
        #pragma unroll
        for (int hf = 0; hf < 2; hf++) {
            int m = wm * 16 + g + hf * 8;
            *(__half2*)(ctx + (size_t)(m * CC + c) * EE + d) =
                __floats2half2_rn(acc[nt][hf * 2], acc[nt][hf * 2 + 1]);
        }
    }
}

// ---------------- host driver ----------------
#define GEMM_SMEM (NSTAGE * 2 * TILE_H * 2)   // 81920 bytes

static void run_gemm(const __half* A, const __half* BT, const float* bias, const float* res,
                     float* Cf, __half* Ch, int M, int N, int K, int gelu) {
    dim3 grid(N / 128, M / 128);
    mma_gemm_f16<<<grid, 256, GEMM_SMEM>>>(A, BT, bias, res, Cf, Ch, M, N, K, gelu);
}

extern "C" void kernel_launch(void* const* d_in, const int* in_sizes, int n_in,
                              void* d_out, int out_size) {
    const float* x_in = (const float*)d_in[0];
    const float* rq_w = (const float*)d_in[1];  const float* rq_b = (const float*)d_in[2];
    const float* rk_w = (const float*)d_in[3];  const float* rk_b = (const float*)d_in[4];
    const float* rv_w = (const float*)d_in[5];  const float* rv_b = (const float*)d_in[6];
    const float* ro_w = (const float*)d_in[7];  const float* ro_b = (const float*)d_in[8];
    const float* cq_w = (const float*)d_in[9];  const float* cq_b = (const float*)d_in[10];
    const float* ck_w = (const float*)d_in[11]; const float* ck_b = (const float*)d_in[12];
    const float* cv_w = (const float*)d_in[13]; const float* cv_b = (const float*)d_in[14];
    const float* co_w = (const float*)d_in[15]; const float* co_b = (const float*)d_in[16];
    const float* f1_w = (const float*)d_in[17]; const float* f1_b = (const float*)d_in[18];
    const float* f2_w = (const float*)d_in[19]; const float* f2_b = (const float*)d_in[20];
    const float* ln1_s = (const float*)d_in[21]; const float* ln1_b = (const float*)d_in[22];
    const float* ln2_s = (const float*)d_in[23]; const float* ln2_b = (const float*)d_in[24];
    const float* ln3_s = (const float*)d_in[25]; const float* ln3_b = (const float*)d_in[26];

    float *px, *paw, *pbias;
    void *vh, *vctx, *vbig, *vwt;
    cudaGetSymbolAddress((void**)&px,    g_x);
    cudaGetSymbolAddress(&vh,    g_h);
    cudaGetSymbolAddress(&vctx,  g_ctx);
    cudaGetSymbolAddress((void**)&paw,   g_aw);
    cudaGetSymbolAddress(&vbig,  g_big);
    cudaGetSymbolAddress(&vwt,   g_wt);
    cudaGetSymbolAddress((void**)&pbias, g_bias);
    __half* ph    = (__half*)vh;
    __half* pctx  = (__half*)vctx;
    __half* pqkv  = (__half*)vbig;
    __half* pffn  = (__half*)vbig;
    __half* pwt   = (__half*)vwt;

    cudaFuncSetAttribute(mma_gemm_f16, cudaFuncAttributeMaxDynamicSharedMemorySize, GEMM_SMEM);

    const float row_scale = 0.015625f;
    const float col_scale = 0.125f;

    const size_t WEE = (size_t)EE * EE;
    __half* rqkvT = pwt;
    __half* roT   = pwt + 3 * WEE;
    __half* cqkvT = pwt + 4 * WEE;
    __half* coT   = pwt + 7 * WEE;
    __half* f1T   = pwt + 8 * WEE;
    __half* f2T   = f1T + (size_t)EE * FF;
    float* biasr = pbias;
    float* biasc = pbias + 2304;

    {
        TPArgs a;
        a.src[0] = rq_w; a.dst[0] = pwt + 0 * WEE; a.scale[0] = row_scale;
        a.src[1] = rk_w; a.dst[1] = pwt + 1 * WEE; a.scale[1] = 1.f;
        a.src[2] = rv_w; a.dst[2] = pwt + 2 * WEE; a.scale[2] = 1.f;
        a.src[3] = ro_w; a.dst[3] = roT;           a.scale[3] = 1.f;
        a.src[4] = cq_w; a.dst[4] = pwt + 4 * WEE; a.scale[4] = col_scale;
        a.src[5] = ck_w; a.dst[5] = pwt + 5 * WEE; a.scale[5] = 1.f;
        a.src[6] = cv_w; a.dst[6] = pwt + 6 * WEE; a.scale[6] = 1.f;
        a.src[7] = co_w; a.dst[7] = coT;           a.scale[7] = 1.f;
        a.src[8] = f1_w; a.dst[8] = f1T;           a.scale[8] = 1.f;
        a.src[9] = f2_w; a.dst[9] = f2T;           a.scale[9] = 1.f;
        dim3 b(32, 8);
        transpose_all_kernel<<<9216, b>>>(a);
    }
    pack_bias_kernel<<<9, 256>>>(rq_b, rk_b, rv_b, row_scale, biasr);
    pack_bias_kernel<<<9, 256>>>(cq_b, ck_b, cv_b, col_scale, biasc);
    { int n4 = MM * EE / 4; copy_kernel<<<(n4 + 255) / 256, 256>>>((const float4*)x_in, (float4*)px, n4); }

    // ===== row attention =====
    ln_kernel<<<MM, 256>>>(px, ln1_s, ln1_b, ph);
    run_gemm(ph, rqkvT, biasr, nullptr, nullptr, pqkv, MM, QLD, EE, 0);    // launch 6 <- ncu
    { dim3 g(4, 4, HH); row_scores_mma<<<g, 256>>>(pqkv, paw); }
    softmax256_kernel<<<HH * CC, 256>>>(paw);
    { dim3 g(2, RR, HH); row_ctx_mma<<<g, 256>>>(paw, pqkv, pctx); }
    run_gemm(pctx, roT, ro_b, px, px, nullptr, MM, EE, EE, 0);

    // ===== column attention =====
    ln_kernel<<<MM, 256>>>(px, ln2_s, ln2_b, ph);
    run_gemm(ph, cqkvT, biasc, nullptr, nullptr, pqkv, MM, QLD, EE, 0);
    { dim3 g(CC, HH); col_scores_mma<<<g, 256>>>(pqkv, paw); }
    { int nrows = HH * CC * RR; softmax64_kernel<<<(nrows * 32 + 255) / 256, 256>>>(paw, nrows); }
    { dim3 g(CC, HH); col_ctx_mma<<<g, 256>>>(paw, pqkv, pctx); }
    run_gemm(pctx, coT, co_b, px, px, nullptr, MM, EE, EE, 0);

    // ===== FFN =====
    ln_kernel<<<MM, 256>>>(px, ln3_s, ln3_b, ph);
    run_gemm(ph, f1T, f1_b, nullptr, nullptr, pffn, MM, FF, EE, 1);
    run_gemm(pffn, f2T, f2_b, px, (float*)d_out, nullptr, MM, EE, FF, 0);
}